// round 12
// baseline (speedup 1.0000x reference)
#include <cuda_runtime.h>
#include <cuda_bf16.h>
#include <cstdint>

// Problem constants (fixed by the reference).
#define LSEQ 8192
#define EDIM 256
#define HDIM 256      // per-direction hidden
#define G4   1024     // 4*HDIM gate rows
#define KTAG 10
#define NCTA 16       // CTAs per direction = one (non-portable) cluster
#define UPB  16       // hidden units per CTA
#define TXBYTES (16 * 8 * 8)  // 16 CTAs x 8 warps x 8B per phase (self incl)
#define TAG_START 8
#define TAG_STOP  9

#define NPROJ 4096          // proj worker blocks (128 m-tiles x 16 n-tiles x 2 dirs)
#define NLSTM 32            // lstm blocks (2 clusters of 16)

// ---------------------------------------------------------------------------
// Scratch (static device globals: allocation-free per harness rules)
// ---------------------------------------------------------------------------
__device__ float g_P[2][LSEQ][G4];      // input projections + biases, per dir
__device__ float g_h[2][LSEQ][HDIM];    // hidden states per position, per dir
__device__ float g_feats[LSEQ][KTAG];   // emission scores
__device__ int   g_pflag[2][LSEQ / 64]; // per-64-position chunk ready counters

__device__ __forceinline__ float tanh_fast(float x) {
    float y;
    asm("tanh.approx.f32 %0, %1;" : "=f"(y) : "f"(x));
    return y;
}
__device__ __forceinline__ float sig_fast(float x) {
    return 0.5f * tanh_fast(0.5f * x) + 0.5f;
}
__device__ __forceinline__ uint32_t smem_u32(const void* p) {
    return (uint32_t)__cvta_generic_to_shared(p);
}
__device__ __forceinline__ uint32_t mapa_rank(uint32_t addr, uint32_t rank) {
    uint32_t r;
    asm("mapa.shared::cluster.u32 %0, %1, %2;" : "=r"(r) : "r"(addr), "r"(rank));
    return r;
}
__device__ __forceinline__ void mbar_wait_parity(uint32_t addr, uint32_t parity) {
    asm volatile(
        "{\n\t"
        ".reg .pred P;\n\t"
        "WLOOP%=:\n\t"
        "mbarrier.try_wait.parity.acquire.cluster.shared::cta.b64 P, [%0], %1;\n\t"
        "@!P bra WLOOP%=;\n\t"
        "}"
        :: "r"(addr), "r"(parity) : "memory");
}
__device__ __forceinline__ void wait_flag16(const int* p) {
    int v;
    do {
        asm volatile("ld.acquire.gpu.b32 %0, [%1];" : "=r"(v) : "l"(p) : "memory");
    } while (v < 16);
}

// ---------------------------------------------------------------------------
// Zero the proj ready-flags (graph replay safety).
// ---------------------------------------------------------------------------
__global__ void zero_flags_kernel() {
    int i = blockIdx.x * blockDim.x + threadIdx.x;
    if (i < 2 * (LSEQ / 64)) (&g_pflag[0][0])[i] = 0;
}

// ---------------------------------------------------------------------------
// Merged kernel: 32 lstm blocks (clusters 0/1 = dir 0/1) + 4096 proj blocks.
//
// proj role (bid >= 32): one 64x64 tile of
//   P[dir][m][n] = sum_k emb[sent[m]][k] * Wih[dir][n][k] + bih[n] + bhh[n]
// Edge chunks first (dir0 ascending m, dir1 descending) so lstm never starves.
//
// lstm role (bid < 32): persistent DSMEM recurrence, fully warp-autonomous:
// warp w owns units {2w, 2w+1} (8 gate rows). Per step, per warp, with NO
// __syncthreads: mbar wait -> dot (4 rows x 16 cols per lane; same LDS/FMA
// profile + reduction tree as R11) -> owner lanes add P + nonlinearity
// (parallel MUFU) -> lanes 0/16 gather 4 gates via shfl.idx -> c/h update ->
// lane 0 packs 8B, shfl-broadcasts -> lanes 0..15 each send ONE st.async.b64
// to their owned destination CTA. Phase completion = all 8 warps of all 16
// CTAs delivered (TXBYTES = 1024), so the consumption-before-overwrite and
// repost causality proofs carry over from the barrier version.
// ---------------------------------------------------------------------------
__global__ void __launch_bounds__(256, 1)
fused_kernel(const int* __restrict__ sent, const float* __restrict__ emb,
             const float* __restrict__ Wih_f, const float* __restrict__ bih_f,
             const float* __restrict__ bhh_f,
             const float* __restrict__ Wih_b, const float* __restrict__ bih_b,
             const float* __restrict__ bhh_b,
             const float* __restrict__ Whh_f, const float* __restrict__ Whh_b)
{
    const int bid = blockIdx.x;
    const int tid = threadIdx.x;

    if (bid >= NLSTM) {
        // =================== proj role ===================
        const int pid = bid - NLSTM;
        const int dir = pid & 1;
        const int k = pid >> 1;
        const int m_tile = dir ? (127 - (k >> 4)) : (k >> 4);
        const int n_tile = k & 15;
        const int m0 = m_tile * 64, n0 = n_tile * 64;

        const float* W  = dir ? Wih_b : Wih_f;
        const float* b1 = dir ? bih_b : bih_f;
        const float* b2 = dir ? bhh_b : bhh_f;
        float* P = &g_P[dir][0][0];

        __shared__ float As[32][72];
        __shared__ float Bs[32][72];

        const int tx = tid & 15, ty = tid >> 4;

        unsigned long long accp[4][2];
#pragma unroll
        for (int i = 0; i < 4; i++) { accp[i][0] = 0ull; accp[i][1] = 0ull; }

        for (int kb = 0; kb < EDIM; kb += 32) {
#pragma unroll
            for (int i = 0; i < 2; i++) {
                int slot = tid + i * 256;
                int ml = slot >> 3, k4 = slot & 7;
                int row = sent[m0 + ml];
                float4 av = *reinterpret_cast<const float4*>(&emb[row * EDIM + kb + k4 * 4]);
                As[k4 * 4 + 0][ml] = av.x; As[k4 * 4 + 1][ml] = av.y;
                As[k4 * 4 + 2][ml] = av.z; As[k4 * 4 + 3][ml] = av.w;
                float4 wv = *reinterpret_cast<const float4*>(&W[(n0 + ml) * EDIM + kb + k4 * 4]);
                Bs[k4 * 4 + 0][ml] = wv.x; Bs[k4 * 4 + 1][ml] = wv.y;
                Bs[k4 * 4 + 2][ml] = wv.z; Bs[k4 * 4 + 3][ml] = wv.w;
            }
            __syncthreads();
#pragma unroll
            for (int kk = 0; kk < 32; kk++) {
                float4 a = *reinterpret_cast<const float4*>(&As[kk][ty * 4]);
                ulonglong2 bq = *reinterpret_cast<const ulonglong2*>(&Bs[kk][tx * 4]);
                float av[4] = {a.x, a.y, a.z, a.w};
#pragma unroll
                for (int i = 0; i < 4; i++) {
                    unsigned long long ad;
                    asm("mov.b64 %0, {%1, %1};" : "=l"(ad) : "f"(av[i]));
                    asm("fma.rn.f32x2 %0, %1, %2, %0;" : "+l"(accp[i][0]) : "l"(ad), "l"(bq.x));
                    asm("fma.rn.f32x2 %0, %1, %2, %0;" : "+l"(accp[i][1]) : "l"(ad), "l"(bq.y));
                }
            }
            __syncthreads();
        }

        float bsum[4];
#pragma unroll
        for (int j = 0; j < 4; j++) bsum[j] = b1[n0 + tx * 4 + j] + b2[n0 + tx * 4 + j];
#pragma unroll
        for (int i = 0; i < 4; i++) {
            float4 o;
            o.x = __uint_as_float((uint32_t)accp[i][0])         + bsum[0];
            o.y = __uint_as_float((uint32_t)(accp[i][0] >> 32)) + bsum[1];
            o.z = __uint_as_float((uint32_t)accp[i][1])         + bsum[2];
            o.w = __uint_as_float((uint32_t)(accp[i][1] >> 32)) + bsum[3];
            *reinterpret_cast<float4*>(&P[(m0 + ty * 4 + i) * G4 + n0 + tx * 4]) = o;
        }

        __threadfence();
        __syncthreads();
        if (tid == 0) atomicAdd(&g_pflag[dir][m_tile], 1);
        return;
    }

    // =================== lstm role ===================
    const int dir = bid >> 4;
    uint32_t myrank;
    asm("mov.u32 %0, %%cluster_ctarank;" : "=r"(myrank));
    const float* __restrict__ Whh = dir ? Whh_b : Whh_f;
    const float* __restrict__ P = &g_P[dir][0][0];
    float* __restrict__ hs = &g_h[dir][0][0];

    // Warp w owns units {2w, 2w+1}. Lane layout: rg = bit4 (gate-pair half),
    // j = lane&15 (16-float column chunk). Each lane: 4 rows x 16 cols.
    const int w = tid >> 5, wlane = tid & 31;
    const int rg = wlane >> 4, j = wlane & 15;
    const int j0 = (int)myrank * UPB;
    const int jrot = (j >> 1) & 3;            // chunk rotation (bank-conflict-free)

    // Lane's 4 rows: rw = 2*g2 + e, g = 2*rg + g2, unit = 2w + e.
    // Global gate row r(rw) = (2*rg + (rw>>1))*256 + j0 + 2w + (rw&1).
    unsigned long long w2[32];
#pragma unroll
    for (int rw = 0; rw < 4; rw++) {
        const int g = 2 * rg + (rw >> 1), e = rw & 1;
        const int r = g * 256 + j0 + 2 * w + e;
        const ulonglong2* wrow = reinterpret_cast<const ulonglong2*>(Whh + (size_t)r * HDIM + j * 16);
#pragma unroll
        for (int t = 0; t < 4; t++) {
            int ct = (t + jrot) & 3;
            ulonglong2 wv = wrow[ct];
            w2[rw * 8 + t * 2 + 0] = wv.x;
            w2[rw * 8 + t * 2 + 1] = wv.y;
        }
    }

    // Post-reduction, lane holds row rw = 2*bit3(j) + bit2(j). Owners j%4==0
    // hold rows {0,1,2,3} at j={0,4,8,12}. Owner's P row:
    const bool owner = ((j & 3) == 0);
    const int rw_own = 2 * ((j >> 3) & 1) + ((j >> 2) & 1);
    const int g_own = 2 * rg + ((j >> 3) & 1);
    const int r_own = g_own * 256 + j0 + 2 * w + ((j >> 2) & 1);
    (void)rw_own;

    __shared__ __align__(16) float sh[2][HDIM];     // assembled h, double buffer
    __shared__ __align__(16) unsigned long long mbar[2];

    const uint32_t mb0 = smem_u32(&mbar[0]);
    const uint32_t mb1 = mb0 + 8;

    if (tid == 0) {
        asm volatile("mbarrier.inval.shared.b64 [%0];" :: "r"(mb0) : "memory");
        asm volatile("mbarrier.inval.shared.b64 [%0];" :: "r"(mb1) : "memory");
        asm volatile("mbarrier.init.shared.b64 [%0], 1;" :: "r"(mb0) : "memory");
        asm volatile("mbarrier.init.shared.b64 [%0], 1;" :: "r"(mb1) : "memory");
        // Pre-post expected tx for h[0] (buf0) and h[1] (buf1): safe, peers
        // only start storing after the cluster sync below.
        asm volatile("mbarrier.arrive.expect_tx.shared.b64 _, [%0], %1;"
                     :: "r"(mb0), "r"((uint32_t)TXBYTES) : "memory");
        asm volatile("mbarrier.arrive.expect_tx.shared.b64 _, [%0], %1;"
                     :: "r"(mb1), "r"((uint32_t)TXBYTES) : "memory");
    }

    // Sender precompute: lane i (i<16) of EVERY warp owns dest (myrank+1+i)&15.
    uint32_t rm0 = 0;
    if (wlane < NCTA) {
        uint32_t d = (myrank + 1 + (uint32_t)wlane) & (NCTA - 1);   // self last
        rm0 = mapa_rank(mb0, d);
    }
    // This warp's 8-byte slice in the destination h buffer.
    const uint32_t dA0 = smem_u32(&sh[0][j0 + 2 * w]) - mb0;
    const uint32_t dA1 = smem_u32(&sh[1][j0 + 2 * w]) - mb0;

    __syncthreads();
    asm volatile("barrier.cluster.arrive.aligned;" ::: "memory");
    asm volatile("barrier.cluster.wait.aligned;" ::: "memory");

    float creg = 0.f;   // cell state, live at lanes 0 and 16 (unit = 2w + bit4)

    // 2-deep input-projection prefetch (gated on proj chunk readiness).
    float pv = 0.f, pvN = 0.f;
    if (owner) {
        wait_flag16(&g_pflag[dir][dir ? (LSEQ / 64 - 1) : 0]);
        const int pos0 = dir ? (LSEQ - 1) : 0;
        pv = __ldcg(&P[(size_t)pos0 * G4 + r_own]);
        const int pos1 = dir ? (LSEQ - 2) : 1;
        pvN = __ldcg(&P[(size_t)pos1 * G4 + r_own]);
    }

    for (int s = 0; s < LSEQ; s++) {
        const int pos = dir ? (LSEQ - 1 - s) : s;
        const int b = s & 1;

        // Issue the P load for step s+2 (two full steps of latency cover).
        float pvNN = 0.f;
        if (owner && s + 2 < LSEQ) {
            const int posNN = dir ? (pos - 2) : (pos + 2);
            if ((posNN & 63) == (dir ? 63 : 0))
                wait_flag16(&g_pflag[dir][posNN >> 6]);
            pvNN = __ldcg(&P[(size_t)posNN * G4 + r_own]);
        }

        float v0 = 0.f, v1 = 0.f, v2 = 0.f, v3 = 0.f;
        if (s > 0) {
            const int pb = (s - 1) & 1;
            const uint32_t parity = (uint32_t)((s - 1) >> 1) & 1u;
            mbar_wait_parity(pb ? mb1 : mb0, parity);

            // Re-post expected tx for h[s+1]: precedes this warp's (warp 0's)
            // send of h[s], which every peer needs before sending h[s+1].
            if (tid == 0 && s + 1 < LSEQ) {
                asm volatile("mbarrier.arrive.expect_tx.shared.b64 _, [%0], %1;"
                             :: "r"(pb ? mb1 : mb0), "r"((uint32_t)TXBYTES) : "memory");
            }

            // h slice: 16 floats at sh[pb][16j..16j+15], 4 x 16B LDS with
            // chunk rotation (t+jrot)&3 -> conflict-free across each phase.
            ulonglong2 hv[4];
            const ulonglong2* hbase = reinterpret_cast<const ulonglong2*>(&sh[pb][j * 16]);
#pragma unroll
            for (int t = 0; t < 4; t++) hv[t] = hbase[(t + jrot) & 3];

            // 4 row-partials, 8 packed FMA each.
#pragma unroll
            for (int rw = 0; rw < 4; rw++) {
                unsigned long long accA = 0ull, accB = 0ull;
#pragma unroll
                for (int t = 0; t < 4; t++) {
                    asm("fma.rn.f32x2 %0, %1, %2, %0;" : "+l"(accA) : "l"(w2[rw * 8 + t * 2 + 0]), "l"(hv[t].x));
                    asm("fma.rn.f32x2 %0, %1, %2, %0;" : "+l"(accB) : "l"(w2[rw * 8 + t * 2 + 1]), "l"(hv[t].y));
                }
                unsigned long long accT;
                asm("add.rn.f32x2 %0, %1, %2;" : "=l"(accT) : "l"(accA), "l"(accB));
                float pr = __uint_as_float((uint32_t)accT) + __uint_as_float((uint32_t)(accT >> 32));
                if (rw == 0) v0 = pr; else if (rw == 1) v1 = pr;
                else if (rw == 2) v2 = pr; else v3 = pr;
            }
        }

        // Split-tree reduction over the 16 j-lanes (bit4 untouched). After
        // it, every lane holds the full sum of row rw = 2*bit3(j)+bit2(j).
        float r0 = __shfl_xor_sync(0xFFFFFFFFu, v0, 8);
        float r1 = __shfl_xor_sync(0xFFFFFFFFu, v1, 8);
        float r2 = __shfl_xor_sync(0xFFFFFFFFu, v2, 8);
        float r3 = __shfl_xor_sync(0xFFFFFFFFu, v3, 8);
        float a, bb;
        if (j & 8) { a = v2 + r2; bb = v3 + r3; }
        else       { a = v0 + r0; bb = v1 + r1; }
        float ra = __shfl_xor_sync(0xFFFFFFFFu, a, 4);
        float rb = __shfl_xor_sync(0xFFFFFFFFu, bb, 4);
        float v = (j & 4) ? (bb + rb) : (a + ra);
        v += __shfl_xor_sync(0xFFFFFFFFu, v, 2);
        v += __shfl_xor_sync(0xFFFFFFFFu, v, 1);

        // Owner lanes: add P and apply the gate nonlinearity (parallel MUFU).
        float sgv = 0.f;
        if (owner) {
            float t = v + pv;
            sgv = (g_own == 2) ? tanh_fast(t) : sig_fast(t);
        }
        pv = pvN; pvN = pvNN;

        // Gather the 4 gates of unit e = bit4 into lanes 0/16:
        //   gi @ 4e, gf @ 8+4e, gg @ 16+4e, go @ 24+4e  (owner lanes).
        const int e4 = (wlane >> 4) * 4;
        float gi = __shfl_sync(0xFFFFFFFFu, sgv, e4);
        float gf = __shfl_sync(0xFFFFFFFFu, sgv, 8 + e4);
        float gg = __shfl_sync(0xFFFFFFFFu, sgv, 16 + e4);
        float go = __shfl_sync(0xFFFFFFFFu, sgv, 24 + e4);

        // Lanes 0 and 16: cell/hidden update for units 2w / 2w+1.
        creg = gf * creg + gi * gg;
        float hvv = go * tanh_fast(creg);

        // Lane 0 packs both h values; broadcast; lanes 0..15 send ONE b64.
        float h1 = __shfl_sync(0xFFFFFFFFu, hvv, 16);
        unsigned long long pk =
            (unsigned long long)__float_as_uint(hvv) |
            ((unsigned long long)__float_as_uint(h1) << 32);
        if (wlane == 0)
            *reinterpret_cast<float2*>(&hs[(size_t)pos * HDIM + j0 + 2 * w]) =
                make_float2(hvv, h1);                      // for feats (off-path)
        pk = __shfl_sync(0xFFFFFFFFu, pk, 0);
        if (wlane < NCTA && s + 1 < LSEQ) {
            const uint32_t dA = (b ? dA1 : dA0) + rm0;
            const uint32_t rmb = rm0 + (b ? 8u : 0u);
            asm volatile(
                "st.async.shared::cluster.mbarrier::complete_tx::bytes.b64 "
                "[%0], %1, [%2];"
                :: "r"(dA), "l"(pk), "r"(rmb) : "memory");
        }
    }

    // Keep the cluster resident until all outgoing traffic has landed.
    asm volatile("barrier.cluster.arrive.aligned;" ::: "memory");
    asm volatile("barrier.cluster.wait.aligned;" ::: "memory");
}

// ---------------------------------------------------------------------------
// feats[t][k] = [hf[t], hb[t]] . W_tag[k] + b_tag[k]
// ---------------------------------------------------------------------------
__global__ __launch_bounds__(64) void feats_kernel(
    const float* __restrict__ Wtag, const float* __restrict__ btag)
{
    __shared__ float shc[512];
    const int t = blockIdx.x;
    const int tid = threadIdx.x;
#pragma unroll
    for (int i = 0; i < 8; i++) {
        int d = tid + 64 * i;
        shc[d] = (d < HDIM) ? g_h[0][t][d] : g_h[1][t][d - HDIM];
    }
    __syncthreads();
    const int wr = tid >> 5, l = tid & 31;
#pragma unroll
    for (int kk = 0; kk < 5; kk++) {
        int k = wr * 5 + kk;
        float ssum = 0.f;
#pragma unroll
        for (int j = 0; j < 16; j++) {
            int d = l + 32 * j;
            ssum += shc[d] * Wtag[k * 512 + d];
        }
#pragma unroll
        for (int off = 16; off >= 1; off >>= 1)
            ssum += __shfl_down_sync(0xFFFFFFFFu, ssum, off);
        if (l == 0) g_feats[t][k] = ssum + btag[k];
    }
}

// ---------------------------------------------------------------------------
// Viterbi max-plus scan + traceback. One warp; backpointers in dynamic smem.
// First-max argmax via a left-priority '>=' tree (depth 4) == jnp.argmax.
// ---------------------------------------------------------------------------
struct VK { float v; int i; };
__device__ __forceinline__ VK vk_cmb(VK a, VK b) {   // a carries lower indices
    VK r; r.v = (a.v >= b.v) ? a.v : b.v; r.i = (a.v >= b.v) ? a.i : b.i; return r;
}

__global__ void viterbi_kernel(const float* __restrict__ trans,
                               float* __restrict__ out, int out_size)
{
    extern __shared__ unsigned char bp[];   // [LSEQ][KTAG]
    const int lane = threadIdx.x;
    const int j = lane < KTAG ? lane : KTAG - 1;

    float Trow[KTAG];
#pragma unroll
    for (int p = 0; p < KTAG; p++) Trow[p] = trans[j * KTAG + p];

    float v = (lane == TAG_START) ? 0.f : -10000.f;
    float fc = g_feats[0][j];

    for (int t = 0; t < LSEQ; t++) {
        float fn = (t + 1 < LSEQ) ? g_feats[t + 1][j] : 0.f;   // prefetch

        VK e[KTAG];
#pragma unroll
        for (int p = 0; p < KTAG; p++) {
            float vp = __shfl_sync(0xFFFFFFFFu, v, p);
            e[p].v = vp + Trow[p]; e[p].i = p;
        }
        VK m01 = vk_cmb(e[0], e[1]), m23 = vk_cmb(e[2], e[3]);
        VK m45 = vk_cmb(e[4], e[5]), m67 = vk_cmb(e[6], e[7]);
        VK m89 = vk_cmb(e[8], e[9]);
        VK mA = vk_cmb(m01, m23), mB = vk_cmb(m45, m67);
        VK best = vk_cmb(vk_cmb(mA, mB), m89);

        if (lane < KTAG) bp[t * KTAG + lane] = (unsigned char)best.i;
        v = best.v + fc;
        fc = fn;
    }

    float term = v + trans[TAG_STOP * KTAG + j];
    VK e[KTAG];
#pragma unroll
    for (int p = 0; p < KTAG; p++) {
        e[p].v = __shfl_sync(0xFFFFFFFFu, term, p); e[p].i = p;
    }
    VK m01 = vk_cmb(e[0], e[1]), m23 = vk_cmb(e[2], e[3]);
    VK m45 = vk_cmb(e[4], e[5]), m67 = vk_cmb(e[6], e[7]);
    VK m89 = vk_cmb(e[8], e[9]);
    VK best = vk_cmb(vk_cmb(vk_cmb(m01, m23), vk_cmb(m45, m67)), m89);
    __syncwarp();

    if (lane == 0) {
        if (out_size > 0) out[0] = best.v;                // score
        int tag = best.i;
        if (out_size > LSEQ) out[LSEQ] = (float)tag;      // path[L-1]
        for (int t = LSEQ - 1; t >= 1; t--) {
            tag = bp[t * KTAG + tag];
            if (out_size > t) out[t] = (float)tag;        // path[t-1] at index t
        }
    }
}

// ---------------------------------------------------------------------------
// Launch
// ---------------------------------------------------------------------------
extern "C" void kernel_launch(void* const* d_in, const int* in_sizes, int n_in,
                              void* d_out, int out_size)
{
    const int*   sent  = (const int*)  d_in[0];
    const float* emb   = (const float*)d_in[1];
    const float* Wih_f = (const float*)d_in[2];
    const float* Whh_f = (const float*)d_in[3];
    const float* bih_f = (const float*)d_in[4];
    const float* bhh_f = (const float*)d_in[5];
    const float* Wih_b = (const float*)d_in[6];
    const float* Whh_b = (const float*)d_in[7];
    const float* bih_b = (const float*)d_in[8];
    const float* bhh_b = (const float*)d_in[9];
    const float* W_tag = (const float*)d_in[10];
    const float* b_tag = (const float*)d_in[11];
    const float* trans = (const float*)d_in[12];
    float* out = (float*)d_out;

    cudaFuncSetAttribute(viterbi_kernel,
                         cudaFuncAttributeMaxDynamicSharedMemorySize,
                         LSEQ * KTAG);
    cudaFuncSetAttribute(fused_kernel,
                         cudaFuncAttributeNonPortableClusterSizeAllowed, 1);

    zero_flags_kernel<<<1, 256>>>();

    {
        cudaLaunchConfig_t cfg = {};
        cfg.gridDim = dim3(NLSTM + NPROJ, 1, 1);   // 4128 = 258 clusters of 16
        cfg.blockDim = dim3(256, 1, 1);
        cfg.dynamicSmemBytes = 0;
        cfg.stream = 0;
        cudaLaunchAttribute attrs[1];
        attrs[0].id = cudaLaunchAttributeClusterDimension;
        attrs[0].val.clusterDim.x = NCTA;
        attrs[0].val.clusterDim.y = 1;
        attrs[0].val.clusterDim.z = 1;
        cfg.attrs = attrs;
        cfg.numAttrs = 1;
        cudaLaunchKernelEx(&cfg, fused_kernel,
                           sent, emb, Wih_f, bih_f, bhh_f,
                           Wih_b, bih_b, bhh_b, Whh_f, Whh_b);
    }

    feats_kernel<<<LSEQ, 64>>>(W_tag, b_tag);
    viterbi_kernel<<<1, 32, LSEQ * KTAG>>>(trans, out, out_size);
}

// round 13
// speedup vs baseline: 1.2057x; 1.2057x over previous
#include <cuda_runtime.h>
#include <cuda_bf16.h>
#include <cstdint>

// Problem constants (fixed by the reference).
#define LSEQ 8192
#define EDIM 256
#define HDIM 256      // per-direction hidden
#define G4   1024     // 4*HDIM gate rows
#define KTAG 10
#define NCTA 16       // CTAs per direction = one (non-portable) cluster
#define UPB  16       // hidden units per CTA
#define TXBYTES (16 * 64)   // 16 source CTAs x 64 bytes each per phase (self incl)
#define TAG_START 8
#define TAG_STOP  9

#define NPROJ 4096          // proj worker blocks (128 m-tiles x 16 n-tiles x 2 dirs)
#define NLSTM 32            // lstm blocks (2 clusters of 16)
#define PAD_DSMEM (120 * 1024)   // forces 1 block/SM (exclusivity for lstm CTAs)

// ---------------------------------------------------------------------------
// Scratch (static device globals: allocation-free per harness rules)
// ---------------------------------------------------------------------------
__device__ float g_P[2][LSEQ][G4];      // input projections + biases, per dir
__device__ float g_h[2][LSEQ][HDIM];    // hidden states per position, per dir
__device__ float g_feats[LSEQ][KTAG];   // emission scores
__device__ int   g_pflag[2][LSEQ / 64]; // per-64-position chunk ready counters

__device__ __forceinline__ float tanh_fast(float x) {
    float y;
    asm("tanh.approx.f32 %0, %1;" : "=f"(y) : "f"(x));
    return y;
}
__device__ __forceinline__ float sig_fast(float x) {
    return 0.5f * tanh_fast(0.5f * x) + 0.5f;
}
__device__ __forceinline__ uint32_t smem_u32(const void* p) {
    return (uint32_t)__cvta_generic_to_shared(p);
}
__device__ __forceinline__ uint32_t mapa_rank(uint32_t addr, uint32_t rank) {
    uint32_t r;
    asm("mapa.shared::cluster.u32 %0, %1, %2;" : "=r"(r) : "r"(addr), "r"(rank));
    return r;
}
__device__ __forceinline__ void mbar_wait_parity(uint32_t addr, uint32_t parity) {
    asm volatile(
        "{\n\t"
        ".reg .pred P;\n\t"
        "WLOOP%=:\n\t"
        "mbarrier.try_wait.parity.acquire.cluster.shared::cta.b64 P, [%0], %1;\n\t"
        "@!P bra WLOOP%=;\n\t"
        "}"
        :: "r"(addr), "r"(parity) : "memory");
}
__device__ __forceinline__ void wait_flag16(const int* p) {
    int v;
    do {
        asm volatile("ld.acquire.gpu.b32 %0, [%1];" : "=r"(v) : "l"(p) : "memory");
    } while (v < 16);
}

// ---------------------------------------------------------------------------
// Zero the proj ready-flags (graph replay safety).
// ---------------------------------------------------------------------------
__global__ void zero_flags_kernel() {
    int i = blockIdx.x * blockDim.x + threadIdx.x;
    if (i < 2 * (LSEQ / 64)) (&g_pflag[0][0])[i] = 0;
}

// ---------------------------------------------------------------------------
// Merged kernel: 32 lstm blocks (clusters 0/1 = dir 0/1) + 4096 proj blocks.
// Every block reserves PAD_DSMEM dynamic smem (unused) so the occupancy
// limiter schedules exactly ONE block per SM: proj workers can never
// co-reside with (and steal issue/L1tex from) the latency-critical lstm CTAs.
//
// proj role (bid >= 32): one 64x64 tile of
//   P[dir][m][n] = sum_k emb[sent[m]][k] * Wih[dir][n][k] + bih[n] + bhh[n]
// Edge chunks first (dir0 ascending m, dir1 descending) so lstm never starves.
//
// lstm role (bid < 32): persistent DSMEM recurrence (R11 structure): dot is
// 4 rows x 16 cols per thread (4x fewer LDS.128 than 1x64), split-tree shfl
// reduction, owner lanes apply gate nonlinearities pre-barrier, ONE
// __syncthreads per step, warp 0 does the short c/h update and lanes 0..15
// each send the 64B h-slice to their owned destination CTA via st.async.v4.
// ---------------------------------------------------------------------------
__global__ void __launch_bounds__(256, 1)
fused_kernel(const int* __restrict__ sent, const float* __restrict__ emb,
             const float* __restrict__ Wih_f, const float* __restrict__ bih_f,
             const float* __restrict__ bhh_f,
             const float* __restrict__ Wih_b, const float* __restrict__ bih_b,
             const float* __restrict__ bhh_b,
             const float* __restrict__ Whh_f, const float* __restrict__ Whh_b)
{
    extern __shared__ char pad_unused[];   // occupancy pad only
    const int bid = blockIdx.x;
    const int tid = threadIdx.x;

    if (bid >= NLSTM) {
        // =================== proj role ===================
        const int pid = bid - NLSTM;
        const int dir = pid & 1;
        const int k = pid >> 1;
        const int m_tile = dir ? (127 - (k >> 4)) : (k >> 4);
        const int n_tile = k & 15;
        const int m0 = m_tile * 64, n0 = n_tile * 64;

        const float* W  = dir ? Wih_b : Wih_f;
        const float* b1 = dir ? bih_b : bih_f;
        const float* b2 = dir ? bhh_b : bhh_f;
        float* P = &g_P[dir][0][0];

        __shared__ float As[32][72];
        __shared__ float Bs[32][72];

        const int tx = tid & 15, ty = tid >> 4;

        unsigned long long accp[4][2];
#pragma unroll
        for (int i = 0; i < 4; i++) { accp[i][0] = 0ull; accp[i][1] = 0ull; }

        for (int kb = 0; kb < EDIM; kb += 32) {
#pragma unroll
            for (int i = 0; i < 2; i++) {
                int slot = tid + i * 256;
                int ml = slot >> 3, k4 = slot & 7;
                int row = sent[m0 + ml];
                float4 av = *reinterpret_cast<const float4*>(&emb[row * EDIM + kb + k4 * 4]);
                As[k4 * 4 + 0][ml] = av.x; As[k4 * 4 + 1][ml] = av.y;
                As[k4 * 4 + 2][ml] = av.z; As[k4 * 4 + 3][ml] = av.w;
                float4 wv = *reinterpret_cast<const float4*>(&W[(n0 + ml) * EDIM + kb + k4 * 4]);
                Bs[k4 * 4 + 0][ml] = wv.x; Bs[k4 * 4 + 1][ml] = wv.y;
                Bs[k4 * 4 + 2][ml] = wv.z; Bs[k4 * 4 + 3][ml] = wv.w;
            }
            __syncthreads();
#pragma unroll
            for (int kk = 0; kk < 32; kk++) {
                float4 a = *reinterpret_cast<const float4*>(&As[kk][ty * 4]);
                ulonglong2 bq = *reinterpret_cast<const ulonglong2*>(&Bs[kk][tx * 4]);
                float av[4] = {a.x, a.y, a.z, a.w};
#pragma unroll
                for (int i = 0; i < 4; i++) {
                    unsigned long long ad;
                    asm("mov.b64 %0, {%1, %1};" : "=l"(ad) : "f"(av[i]));
                    asm("fma.rn.f32x2 %0, %1, %2, %0;" : "+l"(accp[i][0]) : "l"(ad), "l"(bq.x));
                    asm("fma.rn.f32x2 %0, %1, %2, %0;" : "+l"(accp[i][1]) : "l"(ad), "l"(bq.y));
                }
            }
            __syncthreads();
        }

        float bsum[4];
#pragma unroll
        for (int j = 0; j < 4; j++) bsum[j] = b1[n0 + tx * 4 + j] + b2[n0 + tx * 4 + j];
#pragma unroll
        for (int i = 0; i < 4; i++) {
            float4 o;
            o.x = __uint_as_float((uint32_t)accp[i][0])         + bsum[0];
            o.y = __uint_as_float((uint32_t)(accp[i][0] >> 32)) + bsum[1];
            o.z = __uint_as_float((uint32_t)accp[i][1])         + bsum[2];
            o.w = __uint_as_float((uint32_t)(accp[i][1] >> 32)) + bsum[3];
            *reinterpret_cast<float4*>(&P[(m0 + ty * 4 + i) * G4 + n0 + tx * 4]) = o;
        }

        __threadfence();
        __syncthreads();
        if (tid == 0) atomicAdd(&g_pflag[dir][m_tile], 1);
        return;
    }

    // =================== lstm role ===================
    const int dir = bid >> 4;
    uint32_t myrank;
    asm("mov.u32 %0, %%cluster_ctarank;" : "=r"(myrank));
    const float* __restrict__ Whh = dir ? Whh_b : Whh_f;
    const float* __restrict__ P = &g_P[dir][0][0];
    float* __restrict__ hs = &g_h[dir][0][0];

    // Thread layout: i = row-group (4 gate rows 4i..4i+3), j = column chunk.
    const int i = tid >> 4, j = tid & 15;
    const int j0 = (int)myrank * UPB;
    const int jrot = (j >> 1) & 3;            // chunk rotation (bank-conflict-free)

    // Row of the P value this thread owns post-reduction (j&3==0 lanes only).
    const int l_own = 4 * i + (j >> 2);
    const int r_own = (l_own >> 4) * 256 + j0 + (l_own & 15);

    // Weights: 4 rows x 16 cols, chunk order rotated by jrot to match h loads.
    unsigned long long w2[32];
#pragma unroll
    for (int rr = 0; rr < 4; rr++) {
        const int l = 4 * i + rr;
        const int r = (l >> 4) * 256 + j0 + (l & 15);
        const ulonglong2* wrow = reinterpret_cast<const ulonglong2*>(Whh + (size_t)r * HDIM + j * 16);
#pragma unroll
        for (int t = 0; t < 4; t++) {
            int ct = (t + jrot) & 3;
            ulonglong2 wv = wrow[ct];
            w2[rr * 8 + t * 2 + 0] = wv.x;
            w2[rr * 8 + t * 2 + 1] = wv.y;
        }
    }

    __shared__ __align__(16) float sh[2][HDIM];     // assembled h, double buffer
    __shared__ __align__(16) float sgate[UPB * 4];  // [u][g] (post-nonlinearity)
    __shared__ __align__(16) float hstage[UPB];     // warp0 h staging
    __shared__ __align__(16) unsigned long long mbar[2];

    const uint32_t mb0 = smem_u32(&mbar[0]);
    const uint32_t mb1 = mb0 + 8;

    if (tid == 0) {
        asm volatile("mbarrier.inval.shared.b64 [%0];" :: "r"(mb0) : "memory");
        asm volatile("mbarrier.inval.shared.b64 [%0];" :: "r"(mb1) : "memory");
        asm volatile("mbarrier.init.shared.b64 [%0], 1;" :: "r"(mb0) : "memory");
        asm volatile("mbarrier.init.shared.b64 [%0], 1;" :: "r"(mb1) : "memory");
        asm volatile("mbarrier.arrive.expect_tx.shared.b64 _, [%0], %1;"
                     :: "r"(mb0), "r"((uint32_t)TXBYTES) : "memory");
        asm volatile("mbarrier.arrive.expect_tx.shared.b64 _, [%0], %1;"
                     :: "r"(mb1), "r"((uint32_t)TXBYTES) : "memory");
    }

    // Sender precompute: lane i of warp 0 owns destination (myrank+1+i)&15.
    uint32_t rm0 = 0;
    if (tid < NCTA) {
        uint32_t d = (myrank + 1 + (uint32_t)tid) & (NCTA - 1);   // self last
        rm0 = mapa_rank(mb0, d);
    }
    const uint32_t dA0 = smem_u32(&sh[0][j0]) - mb0;
    const uint32_t dA1 = smem_u32(&sh[1][j0]) - mb0;

    __syncthreads();
    asm volatile("barrier.cluster.arrive.aligned;" ::: "memory");
    asm volatile("barrier.cluster.wait.aligned;" ::: "memory");

    float creg = 0.f;   // cell state, warp 0 lanes 0..15 (unit = lane)
    const bool owner = ((j & 3) == 0);

    // 2-deep input-projection prefetch (gated on proj chunk readiness).
    float pv = 0.f, pvN = 0.f;
    if (owner) {
        wait_flag16(&g_pflag[dir][dir ? (LSEQ / 64 - 1) : 0]);
        const int pos0 = dir ? (LSEQ - 1) : 0;
        pv = __ldcg(&P[(size_t)pos0 * G4 + r_own]);
        const int pos1 = dir ? (LSEQ - 2) : 1;
        pvN = __ldcg(&P[(size_t)pos1 * G4 + r_own]);
    }

    for (int s = 0; s < LSEQ; s++) {
        const int pos = dir ? (LSEQ - 1 - s) : s;
        const int b = s & 1;

        // Issue the P load for step s+2 (two full steps of latency cover).
        float pvNN = 0.f;
        if (owner && s + 2 < LSEQ) {
            const int posNN = dir ? (pos - 2) : (pos + 2);
            if ((posNN & 63) == (dir ? 63 : 0))
                wait_flag16(&g_pflag[dir][posNN >> 6]);
            pvNN = __ldcg(&P[(size_t)posNN * G4 + r_own]);
        }

        float v0 = 0.f, v1 = 0.f, v2 = 0.f, v3 = 0.f;
        if (s > 0) {
            const int pb = (s - 1) & 1;
            const uint32_t parity = (uint32_t)((s - 1) >> 1) & 1u;
            mbar_wait_parity(pb ? mb1 : mb0, parity);

            if (tid == 0 && s + 1 < LSEQ) {
                asm volatile("mbarrier.arrive.expect_tx.shared.b64 _, [%0], %1;"
                             :: "r"(pb ? mb1 : mb0), "r"((uint32_t)TXBYTES) : "memory");
            }

            // h slice: 16 floats at sh[pb][16j..16j+15], 4 x 16B LDS with
            // chunk rotation (t+jrot)&3 -> conflict-free across each phase.
            ulonglong2 hv[4];
            const ulonglong2* hbase = reinterpret_cast<const ulonglong2*>(&sh[pb][j * 16]);
#pragma unroll
            for (int t = 0; t < 4; t++) hv[t] = hbase[(t + jrot) & 3];

            // 4 row-partials, 8 packed FMA each.
#pragma unroll
            for (int rr = 0; rr < 4; rr++) {
                unsigned long long accA = 0ull, accB = 0ull;
#pragma unroll
                for (int t = 0; t < 4; t++) {
                    asm("fma.rn.f32x2 %0, %1, %2, %0;" : "+l"(accA) : "l"(w2[rr * 8 + t * 2 + 0]), "l"(hv[t].x));
                    asm("fma.rn.f32x2 %0, %1, %2, %0;" : "+l"(accB) : "l"(w2[rr * 8 + t * 2 + 1]), "l"(hv[t].y));
                }
                unsigned long long accT;
                asm("add.rn.f32x2 %0, %1, %2;" : "=l"(accT) : "l"(accA), "l"(accB));
                float pr = __uint_as_float((uint32_t)accT) + __uint_as_float((uint32_t)(accT >> 32));
                if (rr == 0) v0 = pr; else if (rr == 1) v1 = pr;
                else if (rr == 2) v2 = pr; else v3 = pr;
            }
        }

        // Split-tree reduction over the 16 j-lanes (lane bit4 = i parity,
        // untouched). Owner lanes (j&3==0) end with the sum for row l_own.
        float r0 = __shfl_xor_sync(0xFFFFFFFFu, v0, 8);
        float r1 = __shfl_xor_sync(0xFFFFFFFFu, v1, 8);
        float r2 = __shfl_xor_sync(0xFFFFFFFFu, v2, 8);
        float r3 = __shfl_xor_sync(0xFFFFFFFFu, v3, 8);
        float a, bb;
        if (j & 8) { a = v2 + r2; bb = v3 + r3; }
        else       { a = v0 + r0; bb = v1 + r1; }
        float ra = __shfl_xor_sync(0xFFFFFFFFu, a, 4);
        float rb = __shfl_xor_sync(0xFFFFFFFFu, bb, 4);
        float v = (j & 4) ? (bb + rb) : (a + ra);
        v += __shfl_xor_sync(0xFFFFFFFFu, v, 2);
        v += __shfl_xor_sync(0xFFFFFFFFu, v, 1);

        if (owner) {
            float t = v + pv;
            // sgate[u*4+g] with u = l_own&15, g = l_own>>4.
            sgate[(l_own & 15) * 4 + (l_own >> 4)] =
                ((l_own >> 4) == 2) ? tanh_fast(t) : sig_fast(t);
        }
        pv = pvN; pvN = pvNN;
        __syncthreads();   // the ONLY block-wide barrier per step

        // Warp 0, lanes 0..15: short cell/hidden update + per-lane dest send.
        if (tid < UPB) {
            float4 gt = *reinterpret_cast<const float4*>(&sgate[tid * 4]);
            // gt = (sig_i, sig_f, tanh_g, sig_o)
            creg = gt.y * creg + gt.x * gt.z;
            float hv2 = gt.w * tanh_fast(creg);
            hstage[tid] = hv2;
            hs[(size_t)pos * HDIM + j0 + tid] = hv2;   // for feats (off-path)
            __syncwarp(0x0000FFFFu);
            if (s + 1 < LSEQ) {
                const uint32_t dA = (b ? dA1 : dA0) + rm0;
                const uint32_t rmb = rm0 + (b ? 8u : 0u);
#pragma unroll
                for (int q = 0; q < 4; q++) {
                    uint4 hq = *reinterpret_cast<const uint4*>(&hstage[q * 4]);
                    asm volatile(
                        "st.async.shared::cluster.mbarrier::complete_tx::bytes.v4.b32 "
                        "[%0], {%1, %2, %3, %4}, [%5];"
                        :: "r"(dA + (uint32_t)q * 16), "r"(hq.x), "r"(hq.y),
                           "r"(hq.z), "r"(hq.w), "r"(rmb) : "memory");
                }
            }
        }
    }

    // Keep the cluster resident until all outgoing traffic has landed.
    asm volatile("barrier.cluster.arrive.aligned;" ::: "memory");
    asm volatile("barrier.cluster.wait.aligned;" ::: "memory");
}

// ---------------------------------------------------------------------------
// feats[t][k] = [hf[t], hb[t]] . W_tag[k] + b_tag[k]
// ---------------------------------------------------------------------------
__global__ __launch_bounds__(64) void feats_kernel(
    const float* __restrict__ Wtag, const float* __restrict__ btag)
{
    __shared__ float shc[512];
    const int t = blockIdx.x;
    const int tid = threadIdx.x;
#pragma unroll
    for (int i = 0; i < 8; i++) {
        int d = tid + 64 * i;
        shc[d] = (d < HDIM) ? g_h[0][t][d] : g_h[1][t][d - HDIM];
    }
    __syncthreads();
    const int wr = tid >> 5, l = tid & 31;
#pragma unroll
    for (int kk = 0; kk < 5; kk++) {
        int k = wr * 5 + kk;
        float ssum = 0.f;
#pragma unroll
        for (int j = 0; j < 16; j++) {
            int d = l + 32 * j;
            ssum += shc[d] * Wtag[k * 512 + d];
        }
#pragma unroll
        for (int off = 16; off >= 1; off >>= 1)
            ssum += __shfl_down_sync(0xFFFFFFFFu, ssum, off);
        if (l == 0) g_feats[t][k] = ssum + btag[k];
    }
}

// ---------------------------------------------------------------------------
// Viterbi max-plus scan + traceback. One warp; backpointers in dynamic smem.
// First-max argmax via a left-priority '>=' tree (depth 4) == jnp.argmax.
// ---------------------------------------------------------------------------
struct VK { float v; int i; };
__device__ __forceinline__ VK vk_cmb(VK a, VK b) {   // a carries lower indices
    VK r; r.v = (a.v >= b.v) ? a.v : b.v; r.i = (a.v >= b.v) ? a.i : b.i; return r;
}

__global__ void viterbi_kernel(const float* __restrict__ trans,
                               float* __restrict__ out, int out_size)
{
    extern __shared__ unsigned char bp[];   // [LSEQ][KTAG]
    const int lane = threadIdx.x;
    const int j = lane < KTAG ? lane : KTAG - 1;

    float Trow[KTAG];
#pragma unroll
    for (int p = 0; p < KTAG; p++) Trow[p] = trans[j * KTAG + p];

    float v = (lane == TAG_START) ? 0.f : -10000.f;
    float fc = g_feats[0][j];

    for (int t = 0; t < LSEQ; t++) {
        float fn = (t + 1 < LSEQ) ? g_feats[t + 1][j] : 0.f;   // prefetch

        VK e[KTAG];
#pragma unroll
        for (int p = 0; p < KTAG; p++) {
            float vp = __shfl_sync(0xFFFFFFFFu, v, p);
            e[p].v = vp + Trow[p]; e[p].i = p;
        }
        VK m01 = vk_cmb(e[0], e[1]), m23 = vk_cmb(e[2], e[3]);
        VK m45 = vk_cmb(e[4], e[5]), m67 = vk_cmb(e[6], e[7]);
        VK m89 = vk_cmb(e[8], e[9]);
        VK mA = vk_cmb(m01, m23), mB = vk_cmb(m45, m67);
        VK best = vk_cmb(vk_cmb(mA, mB), m89);

        if (lane < KTAG) bp[t * KTAG + lane] = (unsigned char)best.i;
        v = best.v + fc;
        fc = fn;
    }

    float term = v + trans[TAG_STOP * KTAG + j];
    VK e[KTAG];
#pragma unroll
    for (int p = 0; p < KTAG; p++) {
        e[p].v = __shfl_sync(0xFFFFFFFFu, term, p); e[p].i = p;
    }
    VK m01 = vk_cmb(e[0], e[1]), m23 = vk_cmb(e[2], e[3]);
    VK m45 = vk_cmb(e[4], e[5]), m67 = vk_cmb(e[6], e[7]);
    VK m89 = vk_cmb(e[8], e[9]);
    VK best = vk_cmb(vk_cmb(vk_cmb(m01, m23), vk_cmb(m45, m67)), m89);
    __syncwarp();

    if (lane == 0) {
        if (out_size > 0) out[0] = best.v;                // score
        int tag = best.i;
        if (out_size > LSEQ) out[LSEQ] = (float)tag;      // path[L-1]
        for (int t = LSEQ - 1; t >= 1; t--) {
            tag = bp[t * KTAG + tag];
            if (out_size > t) out[t] = (float)tag;        // path[t-1] at index t
        }
    }
}

// ---------------------------------------------------------------------------
// Launch
// ---------------------------------------------------------------------------
extern "C" void kernel_launch(void* const* d_in, const int* in_sizes, int n_in,
                              void* d_out, int out_size)
{
    const int*   sent  = (const int*)  d_in[0];
    const float* emb   = (const float*)d_in[1];
    const float* Wih_f = (const float*)d_in[2];
    const float* Whh_f = (const float*)d_in[3];
    const float* bih_f = (const float*)d_in[4];
    const float* bhh_f = (const float*)d_in[5];
    const float* Wih_b = (const float*)d_in[6];
    const float* Whh_b = (const float*)d_in[7];
    const float* bih_b = (const float*)d_in[8];
    const float* bhh_b = (const float*)d_in[9];
    const float* W_tag = (const float*)d_in[10];
    const float* b_tag = (const float*)d_in[11];
    const float* trans = (const float*)d_in[12];
    float* out = (float*)d_out;

    cudaFuncSetAttribute(viterbi_kernel,
                         cudaFuncAttributeMaxDynamicSharedMemorySize,
                         LSEQ * KTAG);
    cudaFuncSetAttribute(fused_kernel,
                         cudaFuncAttributeNonPortableClusterSizeAllowed, 1);
    cudaFuncSetAttribute(fused_kernel,
                         cudaFuncAttributeMaxDynamicSharedMemorySize,
                         PAD_DSMEM);

    zero_flags_kernel<<<1, 256>>>();

    {
        cudaLaunchConfig_t cfg = {};
        cfg.gridDim = dim3(NLSTM + NPROJ, 1, 1);   // 4128 = 258 clusters of 16
        cfg.blockDim = dim3(256, 1, 1);
        cfg.dynamicSmemBytes = PAD_DSMEM;          // 1 block/SM exclusivity
        cfg.stream = 0;
        cudaLaunchAttribute attrs[1];
        attrs[0].id = cudaLaunchAttributeClusterDimension;
        attrs[0].val.clusterDim.x = NCTA;
        attrs[0].val.clusterDim.y = 1;
        attrs[0].val.clusterDim.z = 1;
        cfg.attrs = attrs;
        cfg.numAttrs = 1;
        cudaLaunchKernelEx(&cfg, fused_kernel,
                           sent, emb, Wih_f, bih_f, bhh_f,
                           Wih_b, bih_b, bhh_b, Whh_f, Whh_b);
    }

    feats_kernel<<<LSEQ, 64>>>(W_tag, b_tag);
    viterbi_kernel<<<1, 32, LSEQ * KTAG>>>(trans, out, out_size);
}